// round 1
// baseline (speedup 1.0000x reference)
#include <cuda_runtime.h>
#include <math.h>

#define NB 8
#define NE 1024
#define ND 512
#define NQKV 512
#define NH 8
#define NHD 64
#define NBH (NB*NH)         // 64
#define M_ROWS (NB*NE)      // 8192
#define SLAB (NE*NHD)       // 65536
#define LN_EPS 1e-5f
#define ATTN_SCALE 0.044194173824159216f   // 1/sqrt(512)

// ---------------- scratch (device globals; no runtime allocation) -------------
__device__ float g_q[NBH*SLAB];       // (B,H,E,HD) 16MB
__device__ float g_k[NBH*SLAB];
__device__ float g_v[NBH*SLAB];
__device__ float g_ctx[M_ROWS*NQKV];  // (B,E,H,HD) == (8192,512) 16MB

// =============================================================================
// Kernel 1: fused QKV projection.  Y_t = X @ W_t + b_t, scattered to (B,H,E,HD)
// 128x128 tile, BK=16, 256 threads, 8x8 microtile.
// =============================================================================
__global__ __launch_bounds__(256) void gemm_qkv_kernel(
    const float* __restrict__ X,
    const float* __restrict__ Wq, const float* __restrict__ bq,
    const float* __restrict__ Wk, const float* __restrict__ bk,
    const float* __restrict__ Wv, const float* __restrict__ bv)
{
    const int t = blockIdx.z;
    const float* __restrict__ W    = (t==0) ? Wq : ((t==1) ? Wk : Wv);
    const float* __restrict__ bias = (t==0) ? bq : ((t==1) ? bk : bv);
    float* __restrict__ Y          = (t==0) ? g_q : ((t==1) ? g_k : g_v);

    const int bx = blockIdx.x;   // N tile (0..3)
    const int by = blockIdx.y;   // M tile (0..63)
    const int tid = threadIdx.x;
    const int tx = tid & 15;
    const int ty = tid >> 4;

    __shared__ float As[16][128];
    __shared__ float Bs[16][128];

    float acc[8][8];
    #pragma unroll
    for (int i = 0; i < 8; ++i)
        #pragma unroll
        for (int j = 0; j < 8; ++j) acc[i][j] = 0.f;

    for (int kk = 0; kk < ND; kk += 16) {
        // load A tile (128 rows x 16 k), transposed into As[k][m]
        #pragma unroll
        for (int l = 0; l < 2; ++l) {
            int idx = l*256 + tid;
            int row = idx >> 2;          // 0..127
            int c4  = (idx & 3) << 2;    // 0,4,8,12
            float4 v = *(const float4*)(X + (size_t)(by*128 + row)*ND + kk + c4);
            As[c4+0][row] = v.x; As[c4+1][row] = v.y;
            As[c4+2][row] = v.z; As[c4+3][row] = v.w;
        }
        // load B tile (16 k x 128 n)
        #pragma unroll
        for (int l = 0; l < 2; ++l) {
            int idx = l*256 + tid;
            int row = idx >> 5;          // 0..15
            int c4  = (idx & 31) << 2;   // 0..124
            float4 v = *(const float4*)(W + (size_t)(kk + row)*NQKV + bx*128 + c4);
            *(float4*)&Bs[row][c4] = v;
        }
        __syncthreads();

        #pragma unroll
        for (int k = 0; k < 16; ++k) {
            float a[8], b[8];
            float4 a0 = *(float4*)&As[k][ty*4];
            float4 a1 = *(float4*)&As[k][64 + ty*4];
            float4 b0 = *(float4*)&Bs[k][tx*4];
            float4 b1 = *(float4*)&Bs[k][64 + tx*4];
            a[0]=a0.x; a[1]=a0.y; a[2]=a0.z; a[3]=a0.w;
            a[4]=a1.x; a[5]=a1.y; a[6]=a1.z; a[7]=a1.w;
            b[0]=b0.x; b[1]=b0.y; b[2]=b0.z; b[3]=b0.w;
            b[4]=b1.x; b[5]=b1.y; b[6]=b1.z; b[7]=b1.w;
            #pragma unroll
            for (int i = 0; i < 8; ++i)
                #pragma unroll
                for (int j = 0; j < 8; ++j)
                    acc[i][j] = fmaf(a[i], b[j], acc[i][j]);
        }
        __syncthreads();
    }

    // epilogue: bias + scatter to (B,H,E,HD)
    #pragma unroll
    for (int i = 0; i < 8; ++i) {
        int gr = by*128 + ((i < 4) ? (ty*4 + i) : (64 + ty*4 + i - 4));
        int bi = gr >> 10;
        int e  = gr & 1023;
        #pragma unroll
        for (int hj = 0; hj < 2; ++hj) {
            int gc0 = bx*128 + hj*64 + tx*4;
            int h   = gc0 >> 6;
            int hd0 = gc0 & 63;
            float4 r;
            r.x = acc[i][hj*4+0] + bias[gc0+0];
            r.y = acc[i][hj*4+1] + bias[gc0+1];
            r.z = acc[i][hj*4+2] + bias[gc0+2];
            r.w = acc[i][hj*4+3] + bias[gc0+3];
            *(float4*)(Y + ((size_t)(bi*NH + h)*NE + e)*NHD + hd0) = r;
        }
    }
}

// =============================================================================
// Kernel 2: LayerNorm over (E,HD) slab per (b,h) + affine + ReLU, in place.
// grid = (64, 3), 512 threads.
// =============================================================================
__global__ __launch_bounds__(512) void ln_kernel(
    const float* __restrict__ lw0, const float* __restrict__ lb0,
    const float* __restrict__ lw1, const float* __restrict__ lb1,
    const float* __restrict__ lw2, const float* __restrict__ lb2)
{
    const int t  = blockIdx.y;
    const int bh = blockIdx.x;
    float* __restrict__ Y        = (t==0) ? g_q : ((t==1) ? g_k : g_v);
    const float* __restrict__ lw = (t==0) ? lw0 : ((t==1) ? lw1 : lw2);
    const float* __restrict__ lb = (t==0) ? lb0 : ((t==1) ? lb1 : lb2);
    float* base = Y + (size_t)bh * SLAB;

    const int tid = threadIdx.x;
    float s = 0.f, s2 = 0.f;
    for (int i = tid*4; i < SLAB; i += 512*4) {
        float4 v = *(const float4*)(base + i);
        s  += v.x + v.y + v.z + v.w;
        s2 += v.x*v.x + v.y*v.y + v.z*v.z + v.w*v.w;
    }
    #pragma unroll
    for (int o = 16; o > 0; o >>= 1) {
        s  += __shfl_xor_sync(0xffffffffu, s,  o);
        s2 += __shfl_xor_sync(0xffffffffu, s2, o);
    }
    __shared__ float rs[16], rs2[16], bc[2];
    int w = tid >> 5, lane = tid & 31;
    if (lane == 0) { rs[w] = s; rs2[w] = s2; }
    __syncthreads();
    if (w == 0) {
        s  = (lane < 16) ? rs[lane]  : 0.f;
        s2 = (lane < 16) ? rs2[lane] : 0.f;
        #pragma unroll
        for (int o = 8; o > 0; o >>= 1) {
            s  += __shfl_xor_sync(0xffffffffu, s,  o);
            s2 += __shfl_xor_sync(0xffffffffu, s2, o);
        }
        if (lane == 0) {
            float mean = s * (1.f / SLAB);
            float var  = s2 * (1.f / SLAB) - mean*mean;
            bc[0] = mean;
            bc[1] = rsqrtf(var + LN_EPS);
        }
    }
    __syncthreads();
    const float mean = bc[0], rstd = bc[1];

    for (int i = tid*4; i < SLAB; i += 512*4) {
        float4 v = *(const float4*)(base + i);
        float4 g = *(const float4*)(lw + i);
        float4 b = *(const float4*)(lb + i);
        v.x = fmaxf(0.f, (v.x - mean)*rstd*g.x + b.x);
        v.y = fmaxf(0.f, (v.y - mean)*rstd*g.y + b.y);
        v.z = fmaxf(0.f, (v.z - mean)*rstd*g.z + b.z);
        v.w = fmaxf(0.f, (v.w - mean)*rstd*g.w + b.w);
        *(float4*)(base + i) = v;
    }
}

// =============================================================================
// Kernel 3: flash attention per (b,h).  BQ = BKV = 128, HD = 64.
// grid = (E/128, B*H), 256 threads, ~169KB dynamic smem.
// =============================================================================
#define QS_PITCH 65
#define VS_PITCH 68
#define SS_PITCH 132
#define SMEM_ATTN ((128*QS_PITCH + 128*QS_PITCH + 128*VS_PITCH + 128*SS_PITCH)*4)

__global__ __launch_bounds__(256) void attn_kernel()
{
    extern __shared__ float sm[];
    float* Qs = sm;
    float* Ks = Qs + 128*QS_PITCH;
    float* Vs = Ks + 128*QS_PITCH;
    float* Ss = Vs + 128*VS_PITCH;

    const int bh = blockIdx.y;
    const int qb = blockIdx.x;
    const int tid = threadIdx.x;
    const int tx = tid & 15;
    const int ty = tid >> 4;
    const int r0 = ty * 8;

    const float* __restrict__ qg = g_q + (size_t)bh*SLAB + (size_t)qb*128*NHD;
    const float* __restrict__ kg = g_k + (size_t)bh*SLAB;
    const float* __restrict__ vg = g_v + (size_t)bh*SLAB;

    // load Q tile (scale folded in)
    #pragma unroll
    for (int l = 0; l < 8; ++l) {
        int idx = l*256 + tid;
        int row = idx >> 4;
        int c4  = (idx & 15) << 2;
        float4 v = *(const float4*)(qg + row*NHD + c4);
        Qs[row*QS_PITCH + c4 + 0] = v.x * ATTN_SCALE;
        Qs[row*QS_PITCH + c4 + 1] = v.y * ATTN_SCALE;
        Qs[row*QS_PITCH + c4 + 2] = v.z * ATTN_SCALE;
        Qs[row*QS_PITCH + c4 + 3] = v.w * ATTN_SCALE;
    }

    float m_i[8], l_i[8];
    float4 o[8];
    #pragma unroll
    for (int i = 0; i < 8; ++i) {
        m_i[i] = -INFINITY; l_i[i] = 0.f;
        o[i].x = o[i].y = o[i].z = o[i].w = 0.f;
    }

    for (int kt = 0; kt < NE/128; ++kt) {
        const float* kgt = kg + (size_t)kt*128*NHD;
        const float* vgt = vg + (size_t)kt*128*NHD;
        __syncthreads();   // protect previous iteration's Ks/Vs reads
        #pragma unroll
        for (int l = 0; l < 8; ++l) {
            int idx = l*256 + tid;
            int row = idx >> 4;
            int c4  = (idx & 15) << 2;
            float4 kv = *(const float4*)(kgt + row*NHD + c4);
            Ks[row*QS_PITCH + c4 + 0] = kv.x;
            Ks[row*QS_PITCH + c4 + 1] = kv.y;
            Ks[row*QS_PITCH + c4 + 2] = kv.z;
            Ks[row*QS_PITCH + c4 + 3] = kv.w;
            float4 vv = *(const float4*)(vgt + row*NHD + c4);
            *(float4*)&Vs[row*VS_PITCH + c4] = vv;
        }
        __syncthreads();

        // ---- S = Q @ K^T  (thread cols are tx + 16*j : conflict-free K reads)
        float s[8][8];
        #pragma unroll
        for (int i = 0; i < 8; ++i)
            #pragma unroll
            for (int j = 0; j < 8; ++j) s[i][j] = 0.f;

        #pragma unroll 8
        for (int f = 0; f < NHD; ++f) {
            float q[8], kk[8];
            #pragma unroll
            for (int i = 0; i < 8; ++i) q[i]  = Qs[(r0 + i)*QS_PITCH + f];
            #pragma unroll
            for (int j = 0; j < 8; ++j) kk[j] = Ks[(tx + 16*j)*QS_PITCH + f];
            #pragma unroll
            for (int i = 0; i < 8; ++i)
                #pragma unroll
                for (int j = 0; j < 8; ++j)
                    s[i][j] = fmaf(q[i], kk[j], s[i][j]);
        }

        // ---- online softmax (row groups are 16 consecutive lanes)
        #pragma unroll
        for (int i = 0; i < 8; ++i) {
            float tm = s[i][0];
            #pragma unroll
            for (int j = 1; j < 8; ++j) tm = fmaxf(tm, s[i][j]);
            #pragma unroll
            for (int off = 8; off > 0; off >>= 1)
                tm = fmaxf(tm, __shfl_xor_sync(0xffffffffu, tm, off));
            float mn    = fmaxf(m_i[i], tm);
            float alpha = __expf(m_i[i] - mn);
            float rsum  = 0.f;
            #pragma unroll
            for (int j = 0; j < 8; ++j) {
                float p = __expf(s[i][j] - mn);
                s[i][j] = p;
                rsum += p;
            }
            #pragma unroll
            for (int off = 8; off > 0; off >>= 1)
                rsum += __shfl_xor_sync(0xffffffffu, rsum, off);
            l_i[i] = l_i[i]*alpha + rsum;
            m_i[i] = mn;
            o[i].x *= alpha; o[i].y *= alpha; o[i].z *= alpha; o[i].w *= alpha;
            #pragma unroll
            for (int j = 0; j < 8; ++j)
                Ss[(r0 + i)*SS_PITCH + tx + 16*j] = s[i][j];
        }
        __syncthreads();

        // ---- O += P @ V  (each thread: rows r0..r0+7, hd cols tx*4..+3)
        #pragma unroll 4
        for (int c = 0; c < 128; ++c) {
            float4 v = *(float4*)&Vs[c*VS_PITCH + tx*4];
            #pragma unroll
            for (int i = 0; i < 8; ++i) {
                float p = Ss[(r0 + i)*SS_PITCH + c];
                o[i].x = fmaf(p, v.x, o[i].x);
                o[i].y = fmaf(p, v.y, o[i].y);
                o[i].z = fmaf(p, v.z, o[i].z);
                o[i].w = fmaf(p, v.w, o[i].w);
            }
        }
    }

    // epilogue: normalize and write to (B,E,H,HD)
    const int bi = bh >> 3;
    const int h  = bh & 7;
    #pragma unroll
    for (int i = 0; i < 8; ++i) {
        float inv = 1.f / l_i[i];
        int e = qb*128 + r0 + i;
        float4 r;
        r.x = o[i].x * inv; r.y = o[i].y * inv;
        r.z = o[i].z * inv; r.w = o[i].w * inv;
        *(float4*)(g_ctx + ((size_t)(bi*NE + e)*NH + h)*NHD + tx*4) = r;
    }
}

// =============================================================================
// Kernel 4: output projection  out = relu(ctx @ Wo + bo), (8192,512) row-major
// =============================================================================
__global__ __launch_bounds__(256) void gemm_out_kernel(
    const float* __restrict__ Wo, const float* __restrict__ bo,
    float* __restrict__ out)
{
    const int bx = blockIdx.x;
    const int by = blockIdx.y;
    const int tid = threadIdx.x;
    const int tx = tid & 15;
    const int ty = tid >> 4;

    __shared__ float As[16][128];
    __shared__ float Bs[16][128];

    float acc[8][8];
    #pragma unroll
    for (int i = 0; i < 8; ++i)
        #pragma unroll
        for (int j = 0; j < 8; ++j) acc[i][j] = 0.f;

    for (int kk = 0; kk < NQKV; kk += 16) {
        #pragma unroll
        for (int l = 0; l < 2; ++l) {
            int idx = l*256 + tid;
            int row = idx >> 2;
            int c4  = (idx & 3) << 2;
            float4 v = *(const float4*)(g_ctx + (size_t)(by*128 + row)*NQKV + kk + c4);
            As[c4+0][row] = v.x; As[c4+1][row] = v.y;
            As[c4+2][row] = v.z; As[c4+3][row] = v.w;
        }
        #pragma unroll
        for (int l = 0; l < 2; ++l) {
            int idx = l*256 + tid;
            int row = idx >> 5;
            int c4  = (idx & 31) << 2;
            float4 v = *(const float4*)(Wo + (size_t)(kk + row)*ND + bx*128 + c4);
            *(float4*)&Bs[row][c4] = v;
        }
        __syncthreads();

        #pragma unroll
        for (int k = 0; k < 16; ++k) {
            float a[8], b[8];
            float4 a0 = *(float4*)&As[k][ty*4];
            float4 a1 = *(float4*)&As[k][64 + ty*4];
            float4 b0 = *(float4*)&Bs[k][tx*4];
            float4 b1 = *(float4*)&Bs[k][64 + tx*4];
            a[0]=a0.x; a[1]=a0.y; a[2]=a0.z; a[3]=a0.w;
            a[4]=a1.x; a[5]=a1.y; a[6]=a1.z; a[7]=a1.w;
            b[0]=b0.x; b[1]=b0.y; b[2]=b0.z; b[3]=b0.w;
            b[4]=b1.x; b[5]=b1.y; b[6]=b1.z; b[7]=b1.w;
            #pragma unroll
            for (int i = 0; i < 8; ++i)
                #pragma unroll
                for (int j = 0; j < 8; ++j)
                    acc[i][j] = fmaf(a[i], b[j], acc[i][j]);
        }
        __syncthreads();
    }

    #pragma unroll
    for (int i = 0; i < 8; ++i) {
        int gr = by*128 + ((i < 4) ? (ty*4 + i) : (64 + ty*4 + i - 4));
        #pragma unroll
        for (int hj = 0; hj < 2; ++hj) {
            int gc0 = bx*128 + hj*64 + tx*4;
            float4 r;
            r.x = fmaxf(0.f, acc[i][hj*4+0] + bo[gc0+0]);
            r.y = fmaxf(0.f, acc[i][hj*4+1] + bo[gc0+1]);
            r.z = fmaxf(0.f, acc[i][hj*4+2] + bo[gc0+2]);
            r.w = fmaxf(0.f, acc[i][hj*4+3] + bo[gc0+3]);
            *(float4*)(out + (size_t)gr*ND + gc0) = r;
        }
    }
}

// =============================================================================
extern "C" void kernel_launch(void* const* d_in, const int* in_sizes, int n_in,
                              void* d_out, int out_size)
{
    const float* features = (const float*)d_in[0];
    const float* Wq   = (const float*)d_in[1];
    const float* bq   = (const float*)d_in[2];
    const float* lnqw = (const float*)d_in[3];
    const float* lnqb = (const float*)d_in[4];
    const float* Wk   = (const float*)d_in[5];
    const float* bk   = (const float*)d_in[6];
    const float* lnkw = (const float*)d_in[7];
    const float* lnkb = (const float*)d_in[8];
    const float* Wv   = (const float*)d_in[9];
    const float* bv   = (const float*)d_in[10];
    const float* lnvw = (const float*)d_in[11];
    const float* lnvb = (const float*)d_in[12];
    const float* Wo   = (const float*)d_in[13];
    const float* bo   = (const float*)d_in[14];
    float* out = (float*)d_out;

    cudaFuncSetAttribute(attn_kernel,
                         cudaFuncAttributeMaxDynamicSharedMemorySize, SMEM_ATTN);

    gemm_qkv_kernel<<<dim3(NQKV/128, M_ROWS/128, 3), 256>>>(
        features, Wq, bq, Wk, bk, Wv, bv);
    ln_kernel<<<dim3(NBH, 3), 512>>>(lnqw, lnqb, lnkw, lnkb, lnvw, lnvb);
    attn_kernel<<<dim3(NE/128, NBH), 256, SMEM_ATTN>>>();
    gemm_out_kernel<<<dim3(ND/128, M_ROWS/128), 256>>>(Wo, bo, out);
}